// round 9
// baseline (speedup 1.0000x reference)
#include <cuda_runtime.h>
#include <math.h>

// B=8, C=128, N=8192, K=9, PAD=4, DIL=1, STR=1, L=N
#define Bv 8
#define Cv 128
#define Nv 8192
#define Kv 9
#define HALF_K 4
#define TL 128           // l positions per block tile
#define THREADS 256
#define CPB 32           // channels per block
#define NITER 4          // CPB / 8 warps

__global__ __launch_bounds__(THREADS, 5)   // cap regs ~51 -> 5 blocks/SM
void swconv_kernel(const float* __restrict__ x,
                   const float* __restrict__ coords,
                   const float* __restrict__ sigma,
                   const float* __restrict__ weight,
                   float* __restrict__ out)
{
    __shared__ float dwT[Kv][TL];     // [k][l] transposed for aligned float4 reads
    __shared__ float ws[CPB * Kv];

    const int b     = blockIdx.y;
    const int l0g   = blockIdx.x * TL;
    const int cbase = blockIdx.z * CPB;
    const int tid   = threadIdx.x;

    // ---- weights slice ----
    for (int i = tid; i < CPB * Kv; i += THREADS)
        ws[i] = weight[cbase * Kv + i];

    // ---- phase 1: dw[l][k], split across all 256 threads (k halves) ----
    {
        const int l_loc = tid & (TL - 1);
        const int khalf = tid >> 7;           // 0 -> k 0..4, 1 -> k 5..8
        const int l     = l0g + l_loc;
        const float* cb = coords + b * 3 * Nv;
        const float cx = cb[l];
        const float cy = cb[Nv + l];
        const float cz = cb[2 * Nv + l];
        const float inv_sig = 1.0f / sigma[0];
        const int k0 = khalf ? 5 : 0;
        const int k1 = khalf ? Kv : 5;
        for (int k = k0; k < k1; k++) {
            const int idx = l + k - HALF_K;
            float dx, dy, dz;
            if (idx >= 0 && idx < Nv) {
                dx = cb[idx]          - cx;
                dy = cb[Nv + idx]     - cy;
                dz = cb[2 * Nv + idx] - cz;
            } else {
                dx = -cx; dy = -cy; dz = -cz;   // zero-padded coords
            }
            const float sq   = dx * dx + dy * dy + dz * dz;
            const float dist = (sq > 0.0f) ? sqrtf(sq) : 0.0f;
            dwT[k][l_loc] = fmaxf(1.0f - dist * inv_sig, 0.0f);
        }
    }
    __syncthreads();

    const int lane = tid & 31;
    const int w_id = tid >> 5;          // warp -> channel offset within pass
    const int lq   = lane * 4;          // local l of first output
    const int lg   = l0g + lq;          // global l

    const bool interior = (l0g >= HALF_K) && (l0g + TL + HALF_K <= Nv);

    if (interior) {
        const float* xb0 = x + (b * Cv + cbase + w_id) * Nv + lg;  // iter stride 8*Nv
        float*       ob0 = out + (b * Cv + cbase + w_id) * Nv + lg;

        // 1-deep pipeline of the three x quads (no shuffles, no edge lanes)
        float4 a = *reinterpret_cast<const float4*>(xb0 - 4);
        float4 m = *reinterpret_cast<const float4*>(xb0);
        float4 r = *reinterpret_cast<const float4*>(xb0 + 4);

        #pragma unroll
        for (int it = 0; it < NITER; ++it) {
            float4 an, mn, rn;
            if (it < NITER - 1) {
                const float* xn = xb0 + (it + 1) * 8 * Nv;
                an = *reinterpret_cast<const float4*>(xn - 4);
                mn = *reinterpret_cast<const float4*>(xn);
                rn = *reinterpret_cast<const float4*>(xn + 4);
            }

            const float xv[12] = { a.x, a.y, a.z, a.w,
                                   m.x, m.y, m.z, m.w,
                                   r.x, r.y, r.z, r.w };

            const float* wc = &ws[(it * 8 + w_id) * Kv];
            float4 acc = make_float4(0.f, 0.f, 0.f, 0.f);
            #pragma unroll
            for (int k = 0; k < Kv; k++) {
                // dw quad read from smem each use (no 36-reg cache)
                const float4 dqk = *reinterpret_cast<const float4*>(&dwT[k][lq]);
                const float wk = wc[k];       // warp-uniform broadcast
                acc.x = fmaf(xv[k + 0] * dqk.x, wk, acc.x);
                acc.y = fmaf(xv[k + 1] * dqk.y, wk, acc.y);
                acc.z = fmaf(xv[k + 2] * dqk.z, wk, acc.z);
                acc.w = fmaf(xv[k + 3] * dqk.w, wk, acc.w);
            }
            *reinterpret_cast<float4*>(ob0 + it * 8 * Nv) = acc;

            a = an; m = mn; r = rn;
        }
    } else {
        // boundary tiles (2 of 64 in l): guarded path
        #pragma unroll
        for (int it = 0; it < NITER; ++it) {
            const int c = cbase + it * 8 + w_id;
            const float* xb = x + (b * Cv + c) * Nv;
            float xv[12];
            #pragma unroll
            for (int j = 0; j < 12; j++) {
                const int idx = lg - HALF_K + j;
                xv[j] = (idx >= 0 && idx < Nv) ? xb[idx] : 0.0f;
            }
            const float* wc = &ws[(it * 8 + w_id) * Kv];
            float4 acc = make_float4(0.f, 0.f, 0.f, 0.f);
            #pragma unroll
            for (int k = 0; k < Kv; k++) {
                const float4 dqk = *reinterpret_cast<const float4*>(&dwT[k][lq]);
                const float wk = wc[k];
                acc.x = fmaf(xv[k + 0] * dqk.x, wk, acc.x);
                acc.y = fmaf(xv[k + 1] * dqk.y, wk, acc.y);
                acc.z = fmaf(xv[k + 2] * dqk.z, wk, acc.z);
                acc.w = fmaf(xv[k + 3] * dqk.w, wk, acc.w);
            }
            *reinterpret_cast<float4*>(out + (b * Cv + c) * Nv + lg) = acc;
        }
    }
}

extern "C" void kernel_launch(void* const* d_in, const int* in_sizes, int n_in,
                              void* d_out, int out_size)
{
    const float* x      = (const float*)d_in[0];
    const float* coords = (const float*)d_in[1];
    const float* sigma  = (const float*)d_in[2];
    const float* weight = (const float*)d_in[3];
    float* out = (float*)d_out;

    dim3 grid(Nv / TL, Bv, Cv / CPB);   // (64, 8, 4) = 2048 blocks
    swconv_kernel<<<grid, THREADS>>>(x, coords, sigma, weight, out);
}

// round 10
// speedup vs baseline: 1.5236x; 1.5236x over previous
#include <cuda_runtime.h>
#include <math.h>

// B=8, C=128, N=8192, K=9, PAD=4, DIL=1, STR=1, L=N
#define Bv 8
#define Cv 128
#define Nv 8192
#define Kv 9
#define HALF_K 4
#define TL 128           // l positions per block tile
#define THREADS 256
#define CPB 32           // channels per block
#define NITER 4          // CPB / 8 warps

typedef unsigned long long ull;

union F2U { float2 f; ull u; };

__device__ __forceinline__ ull pk2(float lo, float hi) {
    F2U t; t.f = make_float2(lo, hi); return t.u;
}
__device__ __forceinline__ ull mul2(ull a, ull b) {
    ull d; asm("mul.rn.f32x2 %0, %1, %2;" : "=l"(d) : "l"(a), "l"(b)); return d;
}
__device__ __forceinline__ ull fma2(ull a, ull b, ull c) {
    ull d; asm("fma.rn.f32x2 %0, %1, %2, %3;" : "=l"(d) : "l"(a), "l"(b), "l"(c)); return d;
}

__global__ __launch_bounds__(THREADS, 4)
void swconv_kernel(const float* __restrict__ x,
                   const float* __restrict__ coords,
                   const float* __restrict__ sigma,
                   const float* __restrict__ weight,
                   float* __restrict__ out)
{
    __shared__ float  dwT[Kv][TL];       // [k][l] transposed, float4-aligned reads
    __shared__ float2 ws2[CPB * Kv];     // weights pre-duplicated (w,w) -> LDS.64

    const int b     = blockIdx.y;
    const int l0g   = blockIdx.x * TL;
    const int cbase = blockIdx.z * CPB;
    const int tid   = threadIdx.x;

    // ---- weights slice, duplicated for packed math ----
    for (int i = tid; i < CPB * Kv; i += THREADS) {
        const float w = weight[cbase * Kv + i];
        ws2[i] = make_float2(w, w);
    }

    // ---- phase 1: dw[l][k], split across all 256 threads (k halves) ----
    {
        const int l_loc = tid & (TL - 1);
        const int khalf = tid >> 7;           // 0 -> k 0..4, 1 -> k 5..8
        const int l     = l0g + l_loc;
        const float* cb = coords + b * 3 * Nv;
        const float cx = cb[l];
        const float cy = cb[Nv + l];
        const float cz = cb[2 * Nv + l];
        const float inv_sig = 1.0f / sigma[0];
        const int k0 = khalf ? 5 : 0;
        const int k1 = khalf ? Kv : 5;
        for (int k = k0; k < k1; k++) {
            const int idx = l + k - HALF_K;
            float dx, dy, dz;
            if (idx >= 0 && idx < Nv) {
                dx = cb[idx]          - cx;
                dy = cb[Nv + idx]     - cy;
                dz = cb[2 * Nv + idx] - cz;
            } else {
                dx = -cx; dy = -cy; dz = -cz;   // zero-padded coords
            }
            const float sq   = dx * dx + dy * dy + dz * dz;
            // dist = sq * rsqrt(sq) == sqrt(sq); MUFU.RSQ + FMUL, guarded at 0
            const float dist = (sq > 0.0f) ? sq * rsqrtf(sq) : 0.0f;
            dwT[k][l_loc] = fmaxf(fmaf(-dist, inv_sig, 1.0f), 0.0f);
        }
    }
    __syncthreads();

    const int lane = tid & 31;
    const int w_id = tid >> 5;          // warp -> channel offset within pass
    const int lq   = lane * 4;          // local l of first output
    const int lg   = l0g + lq;          // global l

    // distance-weight cache as packed pairs: dqA = outputs (l,l+1), dqB = (l+2,l+3)
    ull dqA[Kv], dqB[Kv];
    #pragma unroll
    for (int k = 0; k < Kv; k++) {
        const float4 d4 = *reinterpret_cast<const float4*>(&dwT[k][lq]);
        dqA[k] = pk2(d4.x, d4.y);
        dqB[k] = pk2(d4.z, d4.w);
    }

    const bool interior = (l0g >= HALF_K) && (l0g + TL + HALF_K <= Nv);

    if (interior) {
        const float* xb0 = x   + (b * Cv + cbase + w_id) * Nv + lg; // stride 8*Nv
        float*       ob0 = out + (b * Cv + cbase + w_id) * Nv + lg;

        #pragma unroll
        for (int it = 0; it < NITER; ++it) {
            const float* xp = xb0 + it * 8 * Nv;
            const float4 a = *reinterpret_cast<const float4*>(xp - 4);
            const float4 m = *reinterpret_cast<const float4*>(xp);
            const float4 r = *reinterpret_cast<const float4*>(xp + 4);
            const float xv[12] = { a.x, a.y, a.z, a.w,
                                   m.x, m.y, m.z, m.w,
                                   r.x, r.y, r.z, r.w };

            const ull* wc2 = reinterpret_cast<const ull*>(&ws2[(it * 8 + w_id) * Kv]);
            ull accA = 0ull, accB = 0ull;
            #pragma unroll
            for (int k = 0; k < Kv; k++) {
                const ull w2 = wc2[k];              // LDS.64, warp-uniform
                const ull xA = pk2(xv[k],     xv[k + 1]);
                const ull xB = pk2(xv[k + 2], xv[k + 3]);
                accA = fma2(mul2(xA, dqA[k]), w2, accA);
                accB = fma2(mul2(xB, dqB[k]), w2, accB);
            }
            F2U ra, rb; ra.u = accA; rb.u = accB;
            *reinterpret_cast<float4*>(ob0 + it * 8 * Nv) =
                make_float4(ra.f.x, ra.f.y, rb.f.x, rb.f.y);
        }
    } else {
        // boundary tiles (2 of 64 in l): guarded scalar path
        #pragma unroll
        for (int it = 0; it < NITER; ++it) {
            const int c = cbase + it * 8 + w_id;
            const float* xb = x + (b * Cv + c) * Nv;
            float xv[12];
            #pragma unroll
            for (int j = 0; j < 12; j++) {
                const int idx = lg - HALF_K + j;
                xv[j] = (idx >= 0 && idx < Nv) ? xb[idx] : 0.0f;
            }
            const ull* wc2 = reinterpret_cast<const ull*>(&ws2[(it * 8 + w_id) * Kv]);
            ull accA = 0ull, accB = 0ull;
            #pragma unroll
            for (int k = 0; k < Kv; k++) {
                const ull w2 = wc2[k];
                const ull xA = pk2(xv[k],     xv[k + 1]);
                const ull xB = pk2(xv[k + 2], xv[k + 3]);
                accA = fma2(mul2(xA, dqA[k]), w2, accA);
                accB = fma2(mul2(xB, dqB[k]), w2, accB);
            }
            F2U ra, rb; ra.u = accA; rb.u = accB;
            *reinterpret_cast<float4*>(out + (b * Cv + c) * Nv + lg) =
                make_float4(ra.f.x, ra.f.y, rb.f.x, rb.f.y);
        }
    }
}

extern "C" void kernel_launch(void* const* d_in, const int* in_sizes, int n_in,
                              void* d_out, int out_size)
{
    const float* x      = (const float*)d_in[0];
    const float* coords = (const float*)d_in[1];
    const float* sigma  = (const float*)d_in[2];
    const float* weight = (const float*)d_in[3];
    float* out = (float*)d_out;

    dim3 grid(Nv / TL, Bv, Cv / CPB);   // (64, 8, 4) = 2048 blocks
    swconv_kernel<<<grid, THREADS>>>(x, coords, sigma, weight, out);
}